// round 12
// baseline (speedup 1.0000x reference)
#include <cuda_runtime.h>
#include <cuda_bf16.h>
#include <math.h>

#define Bn 256
#define Ln 256
#define Cn 128
#define HIDn 128
#define MAXE 4352
#define NT 512           // 16 warps
#define HS 132           // fp32 smem row stride
#define TS 136           // bf16 tile row stride (conflict-free fragment LDS)
#define TILE_HALF (128*TS)   // 17408 bf16 per (hi|lo) half

// ---------------- device scratch ----------------
__device__ int g_ptr[Cn + 1];
__device__ unsigned short g_src[MAXE];   // entry = src | (cnt-1)<<7
__device__ int g_cntmat[Cn * Cn];        // dedup count matrix (zeroed per launch)
// precomputed weight split-tiles: [0,1]=embW chunks, [2..5]=Wl0,Wr0,Wl1,Wr1, [6,7]=pW halves
__device__ __nv_bfloat16 g_wt[8][2 * TILE_HALF];

// ---------------- mma.sync bf16 (base ISA) ----------------
__device__ __forceinline__ void mma_bf16(float* c, const unsigned* a, const unsigned* b) {
    asm volatile("mma.sync.aligned.m16n8k16.row.col.f32.bf16.bf16.f32 "
        "{%0,%1,%2,%3}, {%4,%5,%6,%7}, {%8,%9}, {%0,%1,%2,%3};"
        : "+f"(c[0]), "+f"(c[1]), "+f"(c[2]), "+f"(c[3])
        : "r"(a[0]), "r"(a[1]), "r"(a[2]), "r"(a[3]), "r"(b[0]), "r"(b[1]));
}

// scalar split store (used for x tiles where reads must stay coalesced)
__device__ __forceinline__ void cvt_store(__nv_bfloat16* t, int row, int k, float v) {
    __nv_bfloat16 h = __float2bfloat16(v);
    t[row * TS + k] = h;
    t[TILE_HALF + row * TS + k] = __float2bfloat16(v - __bfloat162float(h));
}

__device__ __forceinline__ unsigned pack_bf2(float a, float b) {
    __nv_bfloat162 h = __floats2bfloat162_rn(a, b);
    return *(unsigned*)&h;
}

// vectorized fp32 smem (stride HS) -> split bf16 tile
__device__ __forceinline__ void cvt_tile_vec(__nv_bfloat16* t, const float* src, int tid) {
    for (int idx = tid; idx < 4096; idx += NT) {
        int r = idx >> 5, kg = (idx & 31) << 2;
        float4 v = *(const float4*)(src + r * HS + kg);
        unsigned h01 = pack_bf2(v.x, v.y);
        unsigned h23 = pack_bf2(v.z, v.w);
        __nv_bfloat162 hh01 = *(__nv_bfloat162*)&h01;
        __nv_bfloat162 hh23 = *(__nv_bfloat162*)&h23;
        unsigned l01 = pack_bf2(v.x - __bfloat162float(hh01.x), v.y - __bfloat162float(hh01.y));
        unsigned l23 = pack_bf2(v.z - __bfloat162float(hh23.x), v.w - __bfloat162float(hh23.y));
        *(uint2*)(t + r * TS + kg) = make_uint2(h01, h23);
        *(uint2*)(t + TILE_HALF + r * TS + kg) = make_uint2(l01, l23);
    }
}

// straight 16B copy of a precomputed weight tile global->smem
__device__ __forceinline__ void copy_tile(__nv_bfloat16* dst, const __nv_bfloat16* src, int tid) {
    uint4* d = (uint4*)dst;
    const uint4* s = (const uint4*)src;
    for (int i = tid; i < 4352; i += NT) d[i] = s[i];
}

// per-warp 32x32 GEMM over K=128 (3-term bf16 split)
__device__ __forceinline__ void warp_gemm(const __nv_bfloat16* tA, const __nv_bfloat16* tB,
                                          float acc[2][4][4], int m0, int n0,
                                          int l4, int kq) {
#pragma unroll 2
    for (int ks = 0; ks < 8; ks++) {
        int k0 = ks * 16 + kq;
        unsigned ah[2][4], al[2][4], bh[4][2], bl[4][2];
#pragma unroll
        for (int mb = 0; mb < 2; mb++) {
            const __nv_bfloat16* p = tA + (m0 + mb * 16 + l4) * TS + k0;
            ah[mb][0] = *(const unsigned*)(p);
            ah[mb][1] = *(const unsigned*)(p + 8 * TS);
            ah[mb][2] = *(const unsigned*)(p + 8);
            ah[mb][3] = *(const unsigned*)(p + 8 * TS + 8);
            al[mb][0] = *(const unsigned*)(p + TILE_HALF);
            al[mb][1] = *(const unsigned*)(p + TILE_HALF + 8 * TS);
            al[mb][2] = *(const unsigned*)(p + TILE_HALF + 8);
            al[mb][3] = *(const unsigned*)(p + TILE_HALF + 8 * TS + 8);
        }
#pragma unroll
        for (int nb = 0; nb < 4; nb++) {
            const __nv_bfloat16* p = tB + (n0 + nb * 8 + l4) * TS + k0;
            bh[nb][0] = *(const unsigned*)(p);
            bh[nb][1] = *(const unsigned*)(p + 8);
            bl[nb][0] = *(const unsigned*)(p + TILE_HALF);
            bl[nb][1] = *(const unsigned*)(p + TILE_HALF + 8);
        }
#pragma unroll
        for (int mb = 0; mb < 2; mb++)
#pragma unroll
            for (int nb = 0; nb < 4; nb++) {
                mma_bf16(acc[mb][nb], ah[mb], bh[nb]);
                mma_bf16(acc[mb][nb], ah[mb], bl[nb]);
                mma_bf16(acc[mb][nb], al[mb], bh[nb]);
            }
    }
}

// 8-dim edge logit (tree-reduced: ~16-cycle chain instead of 32)
__device__ __forceinline__ float logit8(float4 xa, float4 xb, float4 xra, float4 xrb,
                                        float4 a8a, float4 a8b) {
    float t;
    t = xa.x + xra.x; t = t > 0.f ? t : 0.2f * t; float u0 = t * a8a.x;
    t = xa.y + xra.y; t = t > 0.f ? t : 0.2f * t; float u1 = t * a8a.y;
    t = xa.z + xra.z; t = t > 0.f ? t : 0.2f * t; float u2 = t * a8a.z;
    t = xa.w + xra.w; t = t > 0.f ? t : 0.2f * t; float u3 = t * a8a.w;
    t = xb.x + xrb.x; t = t > 0.f ? t : 0.2f * t; float u4 = t * a8b.x;
    t = xb.y + xrb.y; t = t > 0.f ? t : 0.2f * t; float u5 = t * a8b.y;
    t = xb.z + xrb.z; t = t > 0.f ? t : 0.2f * t; float u6 = t * a8b.z;
    t = xb.w + xrb.w; t = t > 0.f ? t : 0.2f * t; float u7 = t * a8b.w;
    return ((u0 + u1) + (u2 + u3)) + ((u4 + u5) + (u6 + u7));
}

// ---------------- setup: blocks 0-7 prep weight tiles, block 8 builds dedup CSR ----------------
__global__ void __launch_bounds__(512) k_setup(const void* ei, int E,
                                               const float* __restrict__ embW,
                                               const float* __restrict__ WlA,
                                               const float* __restrict__ WrA,
                                               const float* __restrict__ pW) {
    int tid = threadIdx.x;
    if (blockIdx.x < 8) {
        int t = blockIdx.x;
        __nv_bfloat16* dst = g_wt[t];
        for (int idx = tid; idx < 16384; idx += 512) {
            int row = idx >> 7, k = idx & 127;
            float v;
            if (t < 2) {
                v = embW[(size_t)(t * 128 + k) * HIDn + row];        // B[j=row][l=k]
            } else if (t < 6) {
                int u = t - 2;
                const float* W = ((u & 1) ? WrA : WlA) + (u >> 1) * HIDn * HIDn;
                v = W[(size_t)k * HIDn + row];                       // B[j_out=row][j_in=k]
            } else {
                v = pW[(size_t)k * Ln + (t - 6) * 128 + row];        // A[l'=row][j=k]
            }
            __nv_bfloat16 h = __float2bfloat16(v);
            dst[row * TS + k] = h;
            dst[TILE_HALF + row * TS + k] = __float2bfloat16(v - __bfloat162float(h));
        }
        return;
    }
    // ---- dedup CSR build (block 8) ----
    __shared__ int degs[Cn];
    __shared__ int base[Cn + 1];
    __shared__ int is64s;
    if (tid < 32) {
        int v = ((const int*)ei)[tid * 2 + 1];
        unsigned ball = __ballot_sync(0xffffffffu, v != 0);
        if (tid == 0) is64s = (ball == 0) ? 1 : 0;
    }
    // zero the count matrix (per-launch: graph replays re-run this)
    for (int i = tid; i < Cn * Cn; i += 512) g_cntmat[i] = 0;
    __syncthreads();
    int is64 = is64s;
    for (int e = tid; e < E; e += 512) {
        int s = is64 ? (int)((const long long*)ei)[e]     : ((const int*)ei)[e];
        int d = is64 ? (int)((const long long*)ei)[E + e] : ((const int*)ei)[E + e];
        atomicAdd(&g_cntmat[d * Cn + s], 1);
    }
    __syncthreads();
    // per-dst distinct-entry counts (self loop adds +1 to (c,c))
    if (tid < Cn) {
        const int* row = g_cntmat + tid * Cn;
        int deg = 0;
        for (int s = 0; s < Cn; s++) {
            int c = row[s] + (s == tid ? 1 : 0);
            deg += (c + 511) >> 9;      // ceil(c/512) entries (0 if c==0)
        }
        degs[tid] = deg;
    }
    __syncthreads();
    if (tid < 32) {  // warp scan over 128 degrees, 4 per lane
        int c0 = degs[tid*4], c1 = degs[tid*4+1], c2 = degs[tid*4+2], c3 = degs[tid*4+3];
        int s = c0 + c1 + c2 + c3;
        int pre = s;
#pragma unroll
        for (int off = 1; off < 32; off <<= 1) {
            int t = __shfl_up_sync(0xffffffffu, pre, off);
            if (tid >= off) pre += t;
        }
        int excl = pre - s;
        base[tid*4] = excl; base[tid*4+1] = excl + c0;
        base[tid*4+2] = excl + c0 + c1; base[tid*4+3] = excl + c0 + c1 + c2;
        if (tid == 31) base[Cn] = pre;
    }
    __syncthreads();
    if (tid <= Cn) g_ptr[tid] = base[tid];
    if (tid < Cn) {
        int p = base[tid];
        const int* row = g_cntmat + tid * Cn;
        for (int s = 0; s < Cn; s++) {
            int c = row[s] + (s == tid ? 1 : 0);
            while (c > 0) {
                int take = c > 512 ? 512 : c;
                g_src[p++] = (unsigned short)(s | ((take - 1) << 7));
                c -= take;
            }
        }
    }
}

// ---------------- GAT layer ----------------
template <bool ATT>
__device__ __forceinline__ void gat_layer(
    float* hs, float* xls, float* xrs,
    __nv_bfloat16* tA, __nv_bfloat16* tB, float* rowbuf,
    const int* sptr, const unsigned short* ssrc,
    const __nv_bfloat16* gWl, const __nv_bfloat16* gWr,
    const float* __restrict__ bl, const float* __restrict__ br,
    const float* __restrict__ att, const float* __restrict__ gbias,
    const float* __restrict__ gamma, const float* __restrict__ beta,
    float* attn_rows, int tid) {

    int warp = tid >> 5, lane = tid & 31;
    int l4 = lane >> 2, kq = 2 * (lane & 3);
    int m0 = (warp & 3) * 32, n0 = (warp >> 2) * 32;

    // A <- hs (vectorized split), B <- precomputed Wl tile
    cvt_tile_vec(tA, hs, tid);
    copy_tile(tB, gWl, tid);
    __syncthreads();

    float accL[2][4][4], accR[2][4][4];
#pragma unroll
    for (int mb = 0; mb < 2; mb++)
#pragma unroll
        for (int nb = 0; nb < 4; nb++)
#pragma unroll
            for (int i = 0; i < 4; i++) { accL[mb][nb][i] = 0.f; accR[mb][nb][i] = 0.f; }

    warp_gemm(tA, tB, accL, m0, n0, l4, kq);
    __syncthreads();
    copy_tile(tB, gWr, tid);
    __syncthreads();
    warp_gemm(tA, tB, accR, m0, n0, l4, kq);
    __syncthreads();   // tiles consumed -> xls/xrs may overwrite

#pragma unroll
    for (int mb = 0; mb < 2; mb++)
#pragma unroll
        for (int nb = 0; nb < 4; nb++) {
            int row = m0 + mb * 16 + l4;
            int col = n0 + nb * 8 + kq;
            float2 bl2 = *(const float2*)(bl + col);
            float2 br2 = *(const float2*)(br + col);
            float2 v;
            v.x = accL[mb][nb][0] + bl2.x; v.y = accL[mb][nb][1] + bl2.y;
            *(float2*)(xls + row * HS + col) = v;
            v.x = accL[mb][nb][2] + bl2.x; v.y = accL[mb][nb][3] + bl2.y;
            *(float2*)(xls + (row + 8) * HS + col) = v;
            v.x = accR[mb][nb][0] + br2.x; v.y = accR[mb][nb][1] + br2.y;
            *(float2*)(xrs + row * HS + col) = v;
            v.x = accR[mb][nb][2] + br2.x; v.y = accR[mb][nb][3] + br2.y;
            *(float2*)(xrs + (row + 8) * HS + col) = v;
        }
    __syncthreads();

    // ---- edge softmax aggregation: 8 dims/lane, 2 dedup-edges per warp-iteration ----
    int half16 = lane >> 4;      // 0: even-offset edge, 1: odd-offset edge
    int li = lane & 15;          // dim-lane (covers dims k8..k8+7, head = li>>2)
    int k8 = li * 8;
    float4 a8a = *(const float4*)(att + k8);
    float4 a8b = *(const float4*)(att + k8 + 4);
    float* rb = rowbuf + warp * 128;

    for (int c = warp; c < Cn; c += 16) {
        int e0 = sptr[c], e1 = sptr[c + 1];
        float4 xra = *(const float4*)(xrs + c * HS + k8);
        float4 xrb = *(const float4*)(xrs + c * HS + k8 + 4);
        float sp = 0.f;
        float4 aca = make_float4(0.f, 0.f, 0.f, 0.f);
        float4 acb = make_float4(0.f, 0.f, 0.f, 0.f);
        for (int e = e0; e < e1; e += 2) {
            int ee = e + half16;
            bool valid = ee < e1;
            unsigned sv = ssrc[valid ? ee : e];
            int s = sv & 127;
            float cntf = (float)((sv >> 7) + 1);
            const float* xp = xls + s * HS + k8;
            float4 xa = *(const float4*)(xp);
            float4 xb = *(const float4*)(xp + 4);
            float v = logit8(xa, xb, xra, xrb, a8a, a8b);
            v += __shfl_xor_sync(0xffffffffu, v, 1);
            v += __shfl_xor_sync(0xffffffffu, v, 2);
            float p = valid ? cntf * __expf(v) : 0.f;
            sp += p;
            aca.x += p * xa.x; aca.y += p * xa.y; aca.z += p * xa.z; aca.w += p * xa.w;
            acb.x += p * xb.x; acb.y += p * xb.y; acb.z += p * xb.z; acb.w += p * xb.w;
        }
        // combine edge-halves (lane li <-> li+16 hold same dims, different edges)
        sp += __shfl_xor_sync(0xffffffffu, sp, 16);
        aca.x += __shfl_xor_sync(0xffffffffu, aca.x, 16);
        aca.y += __shfl_xor_sync(0xffffffffu, aca.y, 16);
        aca.z += __shfl_xor_sync(0xffffffffu, aca.z, 16);
        aca.w += __shfl_xor_sync(0xffffffffu, aca.w, 16);
        acb.x += __shfl_xor_sync(0xffffffffu, acb.x, 16);
        acb.y += __shfl_xor_sync(0xffffffffu, acb.y, 16);
        acb.z += __shfl_xor_sync(0xffffffffu, acb.z, 16);
        acb.w += __shfl_xor_sync(0xffffffffu, acb.w, 16);
        float inv = 1.0f / (sp + 1e-16f);   // per-head denominator (head = li>>2)

        // epilogue: +gat_bias, ELU, residual, LayerNorm over the lane's 8 dims
        float4 gba = *(const float4*)(gbias + k8);
        float4 gbb = *(const float4*)(gbias + k8 + 4);
        float4 ha = *(const float4*)(hs + c * HS + k8);
        float4 hb = *(const float4*)(hs + c * HS + k8 + 4);
        float val[8];
        {
            float o;
            o = aca.x * inv + gba.x; o = o > 0.f ? o : expm1f(o); val[0] = ha.x + o;
            o = aca.y * inv + gba.y; o = o > 0.f ? o : expm1f(o); val[1] = ha.y + o;
            o = aca.z * inv + gba.z; o = o > 0.f ? o : expm1f(o); val[2] = ha.z + o;
            o = aca.w * inv + gba.w; o = o > 0.f ? o : expm1f(o); val[3] = ha.w + o;
            o = acb.x * inv + gbb.x; o = o > 0.f ? o : expm1f(o); val[4] = hb.x + o;
            o = acb.y * inv + gbb.y; o = o > 0.f ? o : expm1f(o); val[5] = hb.y + o;
            o = acb.z * inv + gbb.z; o = o > 0.f ? o : expm1f(o); val[6] = hb.z + o;
            o = acb.w * inv + gbb.w; o = o > 0.f ? o : expm1f(o); val[7] = hb.w + o;
        }
        float s1 = ((val[0] + val[1]) + (val[2] + val[3]))
                 + ((val[4] + val[5]) + (val[6] + val[7]));
        s1 += __shfl_xor_sync(0xffffffffu, s1, 1);
        s1 += __shfl_xor_sync(0xffffffffu, s1, 2);
        s1 += __shfl_xor_sync(0xffffffffu, s1, 4);
        s1 += __shfl_xor_sync(0xffffffffu, s1, 8);
        float mu = s1 * (1.0f / 128.0f);
        float d[8], s2 = 0.f;
#pragma unroll
        for (int i = 0; i < 8; i++) { d[i] = val[i] - mu; s2 += d[i] * d[i]; }
        s2 += __shfl_xor_sync(0xffffffffu, s2, 1);
        s2 += __shfl_xor_sync(0xffffffffu, s2, 2);
        s2 += __shfl_xor_sync(0xffffffffu, s2, 4);
        s2 += __shfl_xor_sync(0xffffffffu, s2, 8);
        float rs = rsqrtf(s2 * (1.0f / 128.0f) + 1e-5f);
        float4 g4a = *(const float4*)(gamma + k8);
        float4 g4b = *(const float4*)(gamma + k8 + 4);
        float4 bea = *(const float4*)(beta + k8);
        float4 beb = *(const float4*)(beta + k8 + 4);
        if (lane < 16) {
            float4 ov;
            ov.x = d[0] * rs * g4a.x + bea.x;
            ov.y = d[1] * rs * g4a.y + bea.y;
            ov.z = d[2] * rs * g4a.z + bea.z;
            ov.w = d[3] * rs * g4a.w + bea.w;
            *(float4*)(hs + c * HS + k8) = ov;
            ov.x = d[4] * rs * g4b.x + beb.x;
            ov.y = d[5] * rs * g4b.y + beb.y;
            ov.z = d[6] * rs * g4b.z + beb.z;
            ov.w = d[7] * rs * g4b.w + beb.w;
            *(float4*)(hs + c * HS + k8 + 4) = ov;
        }

        if (ATT) {
            if (lane < 16) {
                *(float4*)(rb + k8) = make_float4(0.f, 0.f, 0.f, 0.f);
                *(float4*)(rb + k8 + 4) = make_float4(0.f, 0.f, 0.f, 0.f);
            }
            __syncwarp();
            for (int e = e0; e < e1; e += 2) {
                int ee = e + half16;
                bool valid = ee < e1;
                unsigned sv = ssrc[valid ? ee : e];
                int s = sv & 127;
                float cntf = (float)((sv >> 7) + 1);
                const float* xp = xls + s * HS + k8;
                float4 xa = *(const float4*)(xp);
                float4 xb = *(const float4*)(xp + 4);
                float v = logit8(xa, xb, xra, xrb, a8a, a8b);
                v += __shfl_xor_sync(0xffffffffu, v, 1);
                v += __shfl_xor_sync(0xffffffffu, v, 2);
                float w = valid ? cntf * __expf(v) * inv : 0.f;
                // sum over 4 heads (head values replicated x4 in each group)
                w += __shfl_xor_sync(0xffffffffu, w, 4);
                w += __shfl_xor_sync(0xffffffffu, w, 8);
                float whi = __shfl_sync(0xffffffffu, w, 16);
                if (lane == 0) {
                    rb[s] += 0.25f * w;                       // s == src of edge e for lane 0
                    if (e + 1 < e1) rb[ssrc[e + 1] & 127] += 0.25f * whi;
                }
            }
            __syncwarp();
            if (lane < 16) {
                *(float4*)(attn_rows + (size_t)c * 128 + k8) = *(const float4*)(rb + k8);
                *(float4*)(attn_rows + (size_t)c * 128 + k8 + 4) = *(const float4*)(rb + k8 + 4);
            }
        }
    }
    __syncthreads();
}

// ---------------- fully fused kernel ----------------
__global__ void __launch_bounds__(NT, 1) k_fused(
    const float* __restrict__ x,
    const float* __restrict__ embB,
    const float* __restrict__ blA, const float* __restrict__ brA,
    const float* __restrict__ attA, const float* __restrict__ gbA,
    const float* __restrict__ gA, const float* __restrict__ beA,
    const float* __restrict__ pB,
    float* __restrict__ out, int nE) {

    extern __shared__ char sm[];
    float* hs = (float*)sm;                                  // 128x132 fp32 = 67584 B
    char* tiles = sm + 67584;                                // 139264 B
    __nv_bfloat16* tA = (__nv_bfloat16*)tiles;               // hi+lo = 69632 B
    __nv_bfloat16* tB = (__nv_bfloat16*)(tiles + 69632);
    float* xls = (float*)tiles;                              // alias (67584 B)
    float* xrs = (float*)(tiles + 67584);
    float* rowbuf = (float*)(sm + 206848);                   // 8192 B
    int* sptr = (int*)(sm + 215040);                         // 528 B
    unsigned short* ssrc = (unsigned short*)(sm + 215568);   // 8704 B

    int b = blockIdx.x, tid = threadIdx.x;
    int warp = tid >> 5, lane = tid & 31;
    int l4 = lane >> 2, kq = 2 * (lane & 3);
    int m0 = (warp & 3) * 32, n0 = (warp >> 2) * 32;

    for (int i = tid; i <= Cn; i += NT) sptr[i] = g_ptr[i];
    for (int i = tid; i < nE; i += NT) ssrc[i] = g_src[i];

    // ---- embed: hs[c][j] = sum_l x[b][l][c] * embW[l][j] + embB[j]
    {
        float accE[2][4][4];
#pragma unroll
        for (int mb = 0; mb < 2; mb++)
#pragma unroll
            for (int nb = 0; nb < 4; nb++)
#pragma unroll
                for (int i = 0; i < 4; i++) accE[mb][nb][i] = 0.f;

        const float* xb = x + (size_t)b * Ln * Cn;
        for (int chunk = 0; chunk < 2; chunk++) {
            int l0c = chunk * 128;
            for (int idx = tid; idx < 16384; idx += NT) {
                int u = idx >> 7, c = idx & 127;
                cvt_store(tA, c, u, xb[(size_t)(l0c + u) * Cn + c]);  // A[c][l]
            }
            copy_tile(tB, g_wt[chunk], tid);
            __syncthreads();
            warp_gemm(tA, tB, accE, m0, n0, l4, kq);
            __syncthreads();
        }
#pragma unroll
        for (int mb = 0; mb < 2; mb++)
#pragma unroll
            for (int nb = 0; nb < 4; nb++) {
                int row = m0 + mb * 16 + l4;
                int col = n0 + nb * 8 + kq;
                float2 eb2 = *(const float2*)(embB + col);
                float2 v;
                v.x = accE[mb][nb][0] + eb2.x; v.y = accE[mb][nb][1] + eb2.y;
                *(float2*)(hs + row * HS + col) = v;
                v.x = accE[mb][nb][2] + eb2.x; v.y = accE[mb][nb][3] + eb2.y;
                *(float2*)(hs + (row + 8) * HS + col) = v;
            }
        __syncthreads();
    }

    float* attn = out + (size_t)Bn * Ln * Cn + (size_t)b * Cn * Cn;
    gat_layer<false>(hs, xls, xrs, tA, tB, rowbuf, sptr, ssrc,
                     g_wt[2], g_wt[3], blA, brA, attA, gbA, gA, beA, nullptr, tid);
    gat_layer<true>(hs, xls, xrs, tA, tB, rowbuf, sptr, ssrc,
                    g_wt[4], g_wt[5], blA + HIDn, brA + HIDn,
                    attA + 128, gbA + HIDn, gA + HIDn, beA + HIDn, attn, tid);

    // ---- proj: out[b][l][c] = sum_j hs[c][j] * pW[j][l] + pB[l]
    cvt_tile_vec(tB, hs, tid);           // B[n=c][k=j] = hs[c][j]
    float* outb = out + (size_t)b * Ln * Cn;
    for (int half = 0; half < 2; half++) {
        copy_tile(tA, g_wt[6 + half], tid);   // A[m=l'][k=j]
        __syncthreads();
        float accP[2][4][4];
#pragma unroll
        for (int mb = 0; mb < 2; mb++)
#pragma unroll
            for (int nb = 0; nb < 4; nb++)
#pragma unroll
                for (int i = 0; i < 4; i++) accP[mb][nb][i] = 0.f;
        warp_gemm(tA, tB, accP, m0, n0, l4, kq);
#pragma unroll
        for (int mb = 0; mb < 2; mb++)
#pragma unroll
            for (int nb = 0; nb < 4; nb++) {
                int l = half * 128 + m0 + mb * 16 + l4;
                int c = n0 + nb * 8 + kq;
                float pb0 = pB[l], pb1 = pB[l + 8];
                float2 v;
                v.x = accP[mb][nb][0] + pb0; v.y = accP[mb][nb][1] + pb0;
                *(float2*)(outb + (size_t)l * Cn + c) = v;
                v.x = accP[mb][nb][2] + pb1; v.y = accP[mb][nb][3] + pb1;
                *(float2*)(outb + (size_t)(l + 8) * Cn + c) = v;
            }
        __syncthreads();   // before tA overwrite for half 1
    }
}

// ---------------- launch ----------------
extern "C" void kernel_launch(void* const* d_in, const int* in_sizes, int n_in,
                              void* d_out, int out_size) {
    const float* x    = (const float*)d_in[0];
    const void*  ei   = d_in[1];
    const float* embW = (const float*)d_in[2];
    const float* embB = (const float*)d_in[3];
    const float* WlA  = (const float*)d_in[4];
    const float* blA  = (const float*)d_in[5];
    const float* WrA  = (const float*)d_in[6];
    const float* brA  = (const float*)d_in[7];
    const float* attA = (const float*)d_in[8];
    const float* gbA  = (const float*)d_in[9];
    const float* gA   = (const float*)d_in[10];
    const float* beA  = (const float*)d_in[11];
    const float* pW   = (const float*)d_in[12];
    const float* pB   = (const float*)d_in[13];
    float* out = (float*)d_out;

    int E = in_sizes[1] / 2;
    int nE = E + Cn;            // upper bound on dedup CSR size
    if (nE > MAXE) nE = MAXE;

    const int SMEM = 224272;

    cudaFuncSetAttribute(k_fused, cudaFuncAttributeMaxDynamicSharedMemorySize, SMEM);

    k_setup<<<9, 512>>>(ei, E, embW, WlA, WrA, pW);
    k_fused<<<Bn, NT, SMEM>>>(x, embB, blA, brA, attA, gbA, gA, beA, pB, out, nE);
}

// round 14
// speedup vs baseline: 1.2025x; 1.2025x over previous
#include <cuda_runtime.h>
#include <cuda_bf16.h>
#include <math.h>

#define Bn 256
#define Ln 256
#define Cn 128
#define HIDn 128
#define MAXE 4224        // 4096 edges + 128 self loops (exact)
#define NT 1024          // 32 warps
#define HS 132           // fp32 smem row stride
#define TS 136           // bf16 tile row stride (conflict-free fragment LDS)
#define TILE_HALF (128*TS)   // 17408 bf16 per (hi|lo) half

// ---------------- device scratch ----------------
__device__ int g_ptr[Cn + 1];
__device__ unsigned short g_src[MAXE];
// precomputed weight split-tiles: [0,1]=embW chunks, [2..5]=Wl0,Wr0,Wl1,Wr1, [6,7]=pW halves
__device__ __nv_bfloat16 g_wt[8][2 * TILE_HALF];

// ---------------- mma.sync bf16 (base ISA) ----------------
__device__ __forceinline__ void mma_bf16(float* c, const unsigned* a, const unsigned* b) {
    asm volatile("mma.sync.aligned.m16n8k16.row.col.f32.bf16.bf16.f32 "
        "{%0,%1,%2,%3}, {%4,%5,%6,%7}, {%8,%9}, {%0,%1,%2,%3};"
        : "+f"(c[0]), "+f"(c[1]), "+f"(c[2]), "+f"(c[3])
        : "r"(a[0]), "r"(a[1]), "r"(a[2]), "r"(a[3]), "r"(b[0]), "r"(b[1]));
}

// scalar split store (used for x tiles where reads must stay coalesced)
__device__ __forceinline__ void cvt_store(__nv_bfloat16* t, int row, int k, float v) {
    __nv_bfloat16 h = __float2bfloat16(v);
    t[row * TS + k] = h;
    t[TILE_HALF + row * TS + k] = __float2bfloat16(v - __bfloat162float(h));
}

__device__ __forceinline__ unsigned pack_bf2(float a, float b) {
    __nv_bfloat162 h = __floats2bfloat162_rn(a, b);
    return *(unsigned*)&h;
}

// vectorized fp32 smem (stride HS) -> split bf16 tile
__device__ __forceinline__ void cvt_tile_vec(__nv_bfloat16* t, const float* src, int tid) {
    for (int idx = tid; idx < 4096; idx += NT) {
        int r = idx >> 5, kg = (idx & 31) << 2;
        float4 v = *(const float4*)(src + r * HS + kg);
        unsigned h01 = pack_bf2(v.x, v.y);
        unsigned h23 = pack_bf2(v.z, v.w);
        __nv_bfloat162 hh01 = *(__nv_bfloat162*)&h01;
        __nv_bfloat162 hh23 = *(__nv_bfloat162*)&h23;
        unsigned l01 = pack_bf2(v.x - __bfloat162float(hh01.x), v.y - __bfloat162float(hh01.y));
        unsigned l23 = pack_bf2(v.z - __bfloat162float(hh23.x), v.w - __bfloat162float(hh23.y));
        *(uint2*)(t + r * TS + kg) = make_uint2(h01, h23);
        *(uint2*)(t + TILE_HALF + r * TS + kg) = make_uint2(l01, l23);
    }
}

// straight 16B copy of a precomputed weight tile global->smem
__device__ __forceinline__ void copy_tile(__nv_bfloat16* dst, const __nv_bfloat16* src, int tid) {
    uint4* d = (uint4*)dst;
    const uint4* s = (const uint4*)src;
    for (int i = tid; i < 4352; i += NT) d[i] = s[i];
}

// per-warp 16x32 GEMM over K=128 (3-term bf16 split); 32 warps tile 128x128
__device__ __forceinline__ void warp_gemm(const __nv_bfloat16* tA, const __nv_bfloat16* tB,
                                          float acc[4][4], int m0, int n0,
                                          int l4, int kq) {
#pragma unroll
    for (int ks = 0; ks < 8; ks++) {
        int k0 = ks * 16 + kq;
        unsigned ah[4], al[4];
        {
            const __nv_bfloat16* p = tA + (m0 + l4) * TS + k0;
            ah[0] = *(const unsigned*)(p);
            ah[1] = *(const unsigned*)(p + 8 * TS);
            ah[2] = *(const unsigned*)(p + 8);
            ah[3] = *(const unsigned*)(p + 8 * TS + 8);
            al[0] = *(const unsigned*)(p + TILE_HALF);
            al[1] = *(const unsigned*)(p + TILE_HALF + 8 * TS);
            al[2] = *(const unsigned*)(p + TILE_HALF + 8);
            al[3] = *(const unsigned*)(p + TILE_HALF + 8 * TS + 8);
        }
#pragma unroll
        for (int nb = 0; nb < 4; nb++) {
            const __nv_bfloat16* p = tB + (n0 + nb * 8 + l4) * TS + k0;
            unsigned bh[2], bl[2];
            bh[0] = *(const unsigned*)(p);
            bh[1] = *(const unsigned*)(p + 8);
            bl[0] = *(const unsigned*)(p + TILE_HALF);
            bl[1] = *(const unsigned*)(p + TILE_HALF + 8);
            mma_bf16(acc[nb], ah, bh);
            mma_bf16(acc[nb], ah, bl);
            mma_bf16(acc[nb], al, bh);
        }
    }
}

// 8-dim edge logit (tree-reduced)
__device__ __forceinline__ float logit8(float4 xa, float4 xb, float4 xra, float4 xrb,
                                        float4 a8a, float4 a8b) {
    float t;
    t = xa.x + xra.x; t = t > 0.f ? t : 0.2f * t; float u0 = t * a8a.x;
    t = xa.y + xra.y; t = t > 0.f ? t : 0.2f * t; float u1 = t * a8a.y;
    t = xa.z + xra.z; t = t > 0.f ? t : 0.2f * t; float u2 = t * a8a.z;
    t = xa.w + xra.w; t = t > 0.f ? t : 0.2f * t; float u3 = t * a8a.w;
    t = xb.x + xrb.x; t = t > 0.f ? t : 0.2f * t; float u4 = t * a8b.x;
    t = xb.y + xrb.y; t = t > 0.f ? t : 0.2f * t; float u5 = t * a8b.y;
    t = xb.z + xrb.z; t = t > 0.f ? t : 0.2f * t; float u6 = t * a8b.z;
    t = xb.w + xrb.w; t = t > 0.f ? t : 0.2f * t; float u7 = t * a8b.w;
    return ((u0 + u1) + (u2 + u3)) + ((u4 + u5) + (u6 + u7));
}

// ---------------- setup: blocks 0-7 prep weight tiles, block 8 builds CSR ----------------
__global__ void __launch_bounds__(512) k_setup(const void* ei, int E,
                                               const float* __restrict__ embW,
                                               const float* __restrict__ WlA,
                                               const float* __restrict__ WrA,
                                               const float* __restrict__ pW) {
    int tid = threadIdx.x;
    if (blockIdx.x < 8) {
        int t = blockIdx.x;
        __nv_bfloat16* dst = g_wt[t];
        for (int idx = tid; idx < 16384; idx += 512) {
            int row = idx >> 7, k = idx & 127;
            float v;
            if (t < 2) {
                v = embW[(size_t)(t * 128 + k) * HIDn + row];        // B[j=row][l=k]
            } else if (t < 6) {
                int u = t - 2;
                const float* W = ((u & 1) ? WrA : WlA) + (u >> 1) * HIDn * HIDn;
                v = W[(size_t)k * HIDn + row];                       // B[j_out=row][j_in=k]
            } else {
                v = pW[(size_t)k * Ln + (t - 6) * 128 + row];        // A[l'=row][j=k]
            }
            __nv_bfloat16 h = __float2bfloat16(v);
            dst[row * TS + k] = h;
            dst[TILE_HALF + row * TS + k] = __float2bfloat16(v - __bfloat162float(h));
        }
        return;
    }
    // ---- CSR build (block 8) ----
    __shared__ int cnt[Cn];
    __shared__ int base[Cn + 1];
    __shared__ int is64s;
    if (tid < 32) {
        int v = ((const int*)ei)[tid * 2 + 1];
        unsigned ball = __ballot_sync(0xffffffffu, v != 0);
        if (tid == 0) is64s = (ball == 0) ? 1 : 0;
    }
    if (tid < Cn) cnt[tid] = 1;
    __syncthreads();
    int is64 = is64s;
    for (int e = tid; e < E; e += 512) {
        int d = is64 ? (int)((const long long*)ei)[E + e] : ((const int*)ei)[E + e];
        atomicAdd(&cnt[d], 1);
    }
    __syncthreads();
    if (tid < 32) {  // warp scan: 4 counts per lane
        int c0 = cnt[tid*4], c1 = cnt[tid*4+1], c2 = cnt[tid*4+2], c3 = cnt[tid*4+3];
        int s = c0 + c1 + c2 + c3;
        int pre = s;
#pragma unroll
        for (int off = 1; off < 32; off <<= 1) {
            int t = __shfl_up_sync(0xffffffffu, pre, off);
            if (tid >= off) pre += t;
        }
        int excl = pre - s;
        base[tid*4] = excl; base[tid*4+1] = excl + c0;
        base[tid*4+2] = excl + c0 + c1; base[tid*4+3] = excl + c0 + c1 + c2;
        if (tid == 31) base[Cn] = pre;
    }
    __syncthreads();
    if (tid <= Cn) g_ptr[tid] = base[tid];
    if (tid < Cn) cnt[tid] = base[tid];
    __syncthreads();
    for (int e = tid; e < E; e += 512) {
        int s = is64 ? (int)((const long long*)ei)[e]     : ((const int*)ei)[e];
        int d = is64 ? (int)((const long long*)ei)[E + e] : ((const int*)ei)[E + e];
        int p = atomicAdd(&cnt[d], 1);
        g_src[p] = (unsigned short)s;
    }
    __syncthreads();
    if (tid < Cn) {
        int p = atomicAdd(&cnt[tid], 1);
        g_src[p] = (unsigned short)tid;
    }
}

// ---------------- GAT layer ----------------
template <bool ATT>
__device__ __forceinline__ void gat_layer(
    float* hs, float* xls, float* xrs,
    __nv_bfloat16* tA, __nv_bfloat16* tB, float* rowbuf,
    const int* sptr, const unsigned short* ssrc,
    const __nv_bfloat16* gWl, const __nv_bfloat16* gWr,
    const float* __restrict__ bl, const float* __restrict__ br,
    const float* __restrict__ att, const float* __restrict__ gbias,
    const float* __restrict__ gamma, const float* __restrict__ beta,
    float* attn_rows, int tid) {

    int warp = tid >> 5, lane = tid & 31;
    int l4 = lane >> 2, kq = 2 * (lane & 3);
    int m0 = (warp & 7) * 16, n0 = (warp >> 3) * 32;

    // A <- hs (vectorized split), B <- precomputed Wl tile
    cvt_tile_vec(tA, hs, tid);
    copy_tile(tB, gWl, tid);
    __syncthreads();

    float accL[4][4], accR[4][4];
#pragma unroll
    for (int nb = 0; nb < 4; nb++)
#pragma unroll
        for (int i = 0; i < 4; i++) { accL[nb][i] = 0.f; accR[nb][i] = 0.f; }

    warp_gemm(tA, tB, accL, m0, n0, l4, kq);
    __syncthreads();
    copy_tile(tB, gWr, tid);
    __syncthreads();
    warp_gemm(tA, tB, accR, m0, n0, l4, kq);
    __syncthreads();   // tiles consumed -> xls/xrs may overwrite

#pragma unroll
    for (int nb = 0; nb < 4; nb++) {
        int row = m0 + l4;
        int col = n0 + nb * 8 + kq;
        float2 bl2 = *(const float2*)(bl + col);
        float2 br2 = *(const float2*)(br + col);
        float2 v;
        v.x = accL[nb][0] + bl2.x; v.y = accL[nb][1] + bl2.y;
        *(float2*)(xls + row * HS + col) = v;
        v.x = accL[nb][2] + bl2.x; v.y = accL[nb][3] + bl2.y;
        *(float2*)(xls + (row + 8) * HS + col) = v;
        v.x = accR[nb][0] + br2.x; v.y = accR[nb][1] + br2.y;
        *(float2*)(xrs + row * HS + col) = v;
        v.x = accR[nb][2] + br2.x; v.y = accR[nb][3] + br2.y;
        *(float2*)(xrs + (row + 8) * HS + col) = v;
    }
    __syncthreads();

    // ---- edge softmax aggregation: 8 dims/lane, 2 edges per warp-iteration ----
    int half16 = lane >> 4;      // 0: even-offset edge, 1: odd-offset edge
    int li = lane & 15;          // dim-lane (covers dims k8..k8+7, head = li>>2)
    int k8 = li * 8;
    float4 a8a = *(const float4*)(att + k8);
    float4 a8b = *(const float4*)(att + k8 + 4);
    float* rb = rowbuf + warp * 128;

    for (int c = warp; c < Cn; c += 32) {
        int e0 = sptr[c], e1 = sptr[c + 1];
        float4 xra = *(const float4*)(xrs + c * HS + k8);
        float4 xrb = *(const float4*)(xrs + c * HS + k8 + 4);
        float sp = 0.f;
        float4 aca = make_float4(0.f, 0.f, 0.f, 0.f);
        float4 acb = make_float4(0.f, 0.f, 0.f, 0.f);
        for (int e = e0; e < e1; e += 2) {
            int ee = e + half16;
            bool valid = ee < e1;
            int s = ssrc[valid ? ee : e];
            const float* xp = xls + s * HS + k8;
            float4 xa = *(const float4*)(xp);
            float4 xb = *(const float4*)(xp + 4);
            float v = logit8(xa, xb, xra, xrb, a8a, a8b);
            v += __shfl_xor_sync(0xffffffffu, v, 1);
            v += __shfl_xor_sync(0xffffffffu, v, 2);
            float p = valid ? __expf(v) : 0.f;
            sp += p;
            aca.x += p * xa.x; aca.y += p * xa.y; aca.z += p * xa.z; aca.w += p * xa.w;
            acb.x += p * xb.x; acb.y += p * xb.y; acb.z += p * xb.z; acb.w += p * xb.w;
        }
        // combine edge-halves (lane li <-> li+16 hold same dims, different edges)
        sp += __shfl_xor_sync(0xffffffffu, sp, 16);
        aca.x += __shfl_xor_sync(0xffffffffu, aca.x, 16);
        aca.y += __shfl_xor_sync(0xffffffffu, aca.y, 16);
        aca.z += __shfl_xor_sync(0xffffffffu, aca.z, 16);
        aca.w += __shfl_xor_sync(0xffffffffu, aca.w, 16);
        acb.x += __shfl_xor_sync(0xffffffffu, acb.x, 16);
        acb.y += __shfl_xor_sync(0xffffffffu, acb.y, 16);
        acb.z += __shfl_xor_sync(0xffffffffu, acb.z, 16);
        acb.w += __shfl_xor_sync(0xffffffffu, acb.w, 16);
        float inv = 1.0f / (sp + 1e-16f);   // per-head denominator (head = li>>2)

        // epilogue: +gat_bias, ELU, residual, LayerNorm over the lane's 8 dims
        float4 gba = *(const float4*)(gbias + k8);
        float4 gbb = *(const float4*)(gbias + k8 + 4);
        float4 ha = *(const float4*)(hs + c * HS + k8);
        float4 hb = *(const float4*)(hs + c * HS + k8 + 4);
        float val[8];
        {
            float o;
            o = aca.x * inv + gba.x; o = o > 0.f ? o : expm1f(o); val[0] = ha.x + o;
            o = aca.y * inv + gba.y; o = o > 0.f ? o : expm1f(o); val[1] = ha.y + o;
            o = aca.z * inv + gba.z; o = o > 0.f ? o : expm1f(o); val[2] = ha.z + o;
            o = aca.w * inv + gba.w; o = o > 0.f ? o : expm1f(o); val[3] = ha.w + o;
            o = acb.x * inv + gbb.x; o = o > 0.f ? o : expm1f(o); val[4] = hb.x + o;
            o = acb.y * inv + gbb.y; o = o > 0.f ? o : expm1f(o); val[5] = hb.y + o;
            o = acb.z * inv + gbb.z; o = o > 0.f ? o : expm1f(o); val[6] = hb.z + o;
            o = acb.w * inv + gbb.w; o = o > 0.f ? o : expm1f(o); val[7] = hb.w + o;
        }
        float s1 = ((val[0] + val[1]) + (val[2] + val[3]))
                 + ((val[4] + val[5]) + (val[6] + val[7]));
        s1 += __shfl_xor_sync(0xffffffffu, s1, 1);
        s1 += __shfl_xor_sync(0xffffffffu, s1, 2);
        s1 += __shfl_xor_sync(0xffffffffu, s1, 4);
        s1 += __shfl_xor_sync(0xffffffffu, s1, 8);
        float mu = s1 * (1.0f / 128.0f);
        float d[8], s2 = 0.f;
#pragma unroll
        for (int i = 0; i < 8; i++) { d[i] = val[i] - mu; s2 += d[i] * d[i]; }
        s2 += __shfl_xor_sync(0xffffffffu, s2, 1);
        s2 += __shfl_xor_sync(0xffffffffu, s2, 2);
        s2 += __shfl_xor_sync(0xffffffffu, s2, 4);
        s2 += __shfl_xor_sync(0xffffffffu, s2, 8);
        float rs = rsqrtf(s2 * (1.0f / 128.0f) + 1e-5f);
        float4 g4a = *(const float4*)(gamma + k8);
        float4 g4b = *(const float4*)(gamma + k8 + 4);
        float4 bea = *(const float4*)(beta + k8);
        float4 beb = *(const float4*)(beta + k8 + 4);
        if (lane < 16) {
            float4 ov;
            ov.x = d[0] * rs * g4a.x + bea.x;
            ov.y = d[1] * rs * g4a.y + bea.y;
            ov.z = d[2] * rs * g4a.z + bea.z;
            ov.w = d[3] * rs * g4a.w + bea.w;
            *(float4*)(hs + c * HS + k8) = ov;
            ov.x = d[4] * rs * g4b.x + beb.x;
            ov.y = d[5] * rs * g4b.y + beb.y;
            ov.z = d[6] * rs * g4b.z + beb.z;
            ov.w = d[7] * rs * g4b.w + beb.w;
            *(float4*)(hs + c * HS + k8 + 4) = ov;
        }

        if (ATT) {
            if (lane < 16) {
                *(float4*)(rb + k8) = make_float4(0.f, 0.f, 0.f, 0.f);
                *(float4*)(rb + k8 + 4) = make_float4(0.f, 0.f, 0.f, 0.f);
            }
            __syncwarp();
            for (int e = e0; e < e1; e += 2) {
                int ee = e + half16;
                bool valid = ee < e1;
                int s = ssrc[valid ? ee : e];
                const float* xp = xls + s * HS + k8;
                float4 xa = *(const float4*)(xp);
                float4 xb = *(const float4*)(xp + 4);
                float v = logit8(xa, xb, xra, xrb, a8a, a8b);
                v += __shfl_xor_sync(0xffffffffu, v, 1);
                v += __shfl_xor_sync(0xffffffffu, v, 2);
                float w = valid ? __expf(v) * inv : 0.f;
                // sum over 4 heads (head values replicated x4 in each group)
                w += __shfl_xor_sync(0xffffffffu, w, 4);
                w += __shfl_xor_sync(0xffffffffu, w, 8);
                float whi = __shfl_sync(0xffffffffu, w, 16);
                if (lane == 0) {
                    rb[s] += 0.25f * w;                       // s == ssrc[e] for lane 0
                    if (e + 1 < e1) rb[ssrc[e + 1]] += 0.25f * whi;
                }
            }
            __syncwarp();
            if (lane < 16) {
                *(float4*)(attn_rows + (size_t)c * 128 + k8) = *(const float4*)(rb + k8);
                *(float4*)(attn_rows + (size_t)c * 128 + k8 + 4) = *(const float4*)(rb + k8 + 4);
            }
        }
    }
    __syncthreads();
}

// ---------------- fully fused kernel ----------------
__global__ void __launch_bounds__(NT, 1) k_fused(
    const float* __restrict__ x,
    const float* __restrict__ embB,
    const float* __restrict__ blA, const float* __restrict__ brA,
    const float* __restrict__ attA, const float* __restrict__ gbA,
    const float* __restrict__ gA, const float* __restrict__ beA,
    const float* __restrict__ pB,
    float* __restrict__ out, int nE) {

    extern __shared__ char sm[];
    float* hs = (float*)sm;                                  // 128x132 fp32 = 67584 B
    char* tiles = sm + 67584;                                // 139264 B
    __nv_bfloat16* tA = (__nv_bfloat16*)tiles;               // hi+lo = 69632 B
    __nv_bfloat16* tB = (__nv_bfloat16*)(tiles + 69632);
    float* xls = (float*)tiles;                              // alias (67584 B)
    float* xrs = (float*)(tiles + 69632);                    // alias tB
    float* rowbuf = (float*)(sm + 206848);                   // 32*128*4 = 16384 B
    int* sptr = (int*)(sm + 223232);                         // 528 B
    unsigned short* ssrc = (unsigned short*)(sm + 223760);   // 8448 B -> end 232208

    int b = blockIdx.x, tid = threadIdx.x;
    int warp = tid >> 5, lane = tid & 31;
    int l4 = lane >> 2, kq = 2 * (lane & 3);
    int m0 = (warp & 7) * 16, n0 = (warp >> 3) * 32;

    for (int i = tid; i <= Cn; i += NT) sptr[i] = g_ptr[i];
    for (int i = tid; i < nE; i += NT) ssrc[i] = g_src[i];

    // ---- embed: hs[c][j] = sum_l x[b][l][c] * embW[l][j] + embB[j]
    {
        float accE[4][4];
#pragma unroll
        for (int nb = 0; nb < 4; nb++)
#pragma unroll
            for (int i = 0; i < 4; i++) accE[nb][i] = 0.f;

        const float* xb = x + (size_t)b * Ln * Cn;
        for (int chunk = 0; chunk < 2; chunk++) {
            int l0c = chunk * 128;
            for (int idx = tid; idx < 16384; idx += NT) {
                int u = idx >> 7, c = idx & 127;
                cvt_store(tA, c, u, xb[(size_t)(l0c + u) * Cn + c]);  // A[c][l]
            }
            copy_tile(tB, g_wt[chunk], tid);
            __syncthreads();
            warp_gemm(tA, tB, accE, m0, n0, l4, kq);
            __syncthreads();
        }
#pragma unroll
        for (int nb = 0; nb < 4; nb++) {
            int row = m0 + l4;
            int col = n0 + nb * 8 + kq;
            float2 eb2 = *(const float2*)(embB + col);
            float2 v;
            v.x = accE[nb][0] + eb2.x; v.y = accE[nb][1] + eb2.y;
            *(float2*)(hs + row * HS + col) = v;
            v.x = accE[nb][2] + eb2.x; v.y = accE[nb][3] + eb2.y;
            *(float2*)(hs + (row + 8) * HS + col) = v;
        }
        __syncthreads();
    }

    float* attn = out + (size_t)Bn * Ln * Cn + (size_t)b * Cn * Cn;
    gat_layer<false>(hs, xls, xrs, tA, tB, rowbuf, sptr, ssrc,
                     g_wt[2], g_wt[3], blA, brA, attA, gbA, gA, beA, nullptr, tid);
    gat_layer<true>(hs, xls, xrs, tA, tB, rowbuf, sptr, ssrc,
                    g_wt[4], g_wt[5], blA + HIDn, brA + HIDn,
                    attA + 128, gbA + HIDn, gA + HIDn, beA + HIDn, attn, tid);

    // ---- proj: out[b][l][c] = sum_j hs[c][j] * pW[j][l] + pB[l]
    cvt_tile_vec(tB, hs, tid);           // B[n=c][k=j] = hs[c][j]
    float* outb = out + (size_t)b * Ln * Cn;
    for (int half = 0; half < 2; half++) {
        copy_tile(tA, g_wt[6 + half], tid);   // A[m=l'][k=j]
        __syncthreads();
        float accP[4][4];
#pragma unroll
        for (int nb = 0; nb < 4; nb++)
#pragma unroll
            for (int i = 0; i < 4; i++) accP[nb][i] = 0.f;
        warp_gemm(tA, tB, accP, m0, n0, l4, kq);
#pragma unroll
        for (int nb = 0; nb < 4; nb++) {
            int l = half * 128 + m0 + l4;
            int c = n0 + nb * 8 + kq;
            float pb0 = pB[l], pb1 = pB[l + 8];
            float2 v;
            v.x = accP[nb][0] + pb0; v.y = accP[nb][1] + pb0;
            *(float2*)(outb + (size_t)l * Cn + c) = v;
            v.x = accP[nb][2] + pb1; v.y = accP[nb][3] + pb1;
            *(float2*)(outb + (size_t)(l + 8) * Cn + c) = v;
        }
        __syncthreads();   // before tA overwrite for half 1
    }
}

// ---------------- launch ----------------
extern "C" void kernel_launch(void* const* d_in, const int* in_sizes, int n_in,
                              void* d_out, int out_size) {
    const float* x    = (const float*)d_in[0];
    const void*  ei   = d_in[1];
    const float* embW = (const float*)d_in[2];
    const float* embB = (const float*)d_in[3];
    const float* WlA  = (const float*)d_in[4];
    const float* blA  = (const float*)d_in[5];
    const float* WrA  = (const float*)d_in[6];
    const float* brA  = (const float*)d_in[7];
    const float* attA = (const float*)d_in[8];
    const float* gbA  = (const float*)d_in[9];
    const float* gA   = (const float*)d_in[10];
    const float* beA  = (const float*)d_in[11];
    const float* pW   = (const float*)d_in[12];
    const float* pB   = (const float*)d_in[13];
    float* out = (float*)d_out;

    int E = in_sizes[1] / 2;
    int nE = E + Cn;
    if (nE > MAXE) nE = MAXE;

    const int SMEM = 232208;

    cudaFuncSetAttribute(k_fused, cudaFuncAttributeMaxDynamicSharedMemorySize, SMEM);

    k_setup<<<9, 512>>>(ei, E, embW, WlA, WrA, pW);
    k_fused<<<Bn, NT, SMEM>>>(x, embB, blA, brA, attA, gbA, gA, beA, pB, out, nE);
}